// round 12
// baseline (speedup 1.0000x reference)
#include <cuda_runtime.h>

// Two-kernel split: dense GEMV1 and sparse GEMV2 each run at their
// individually proven-best configuration, eliminating the wave-lockstep
// phase correlation that throttled the fused kernel's sparse phase.
//   Kernel A: h = relu(x[b,:] @ w1[b,:,:] + b1[b,:])  -> g_h   (R6 geometry)
//   Kernel B: out = h @ w2[b,:,:] + b2[b,:], skipping w2 rows with h[j]==0
//             via predicated affine loads                       (R9 geometry)
// Extra traffic: 4MB h write + 4MB h read (~1.2us) vs clean phase separation.

#define B_DIM 4096
#define D_DIM 128
#define H_DIM 256
#define C_DIM 64

__device__ float g_h[B_DIM * H_DIM];   // 4 MB intermediate activations

// ======================== Kernel A: dense GEMV1 ==========================
__global__ void __launch_bounds__(128, 12) gemv1_kernel(
    const float* __restrict__ x,
    const float* __restrict__ w1,
    const float* __restrict__ b1)
{
    const int l = threadIdx.x;       // 0..127
    const int b = blockIdx.x;

    __shared__ float  x_s[D_DIM];
    __shared__ float4 part[128];

    x_s[l] = x[(size_t)b * D_DIM + l];
    __syncthreads();

    // w1[b] as float4[128][64]. Thread: (dchunk = l>>6, g = l&63).
    // 64 float4 loads/thread, warp-contiguous 1024B rows. (R6, proven 86.2%.)
    {
        const float4* w1v = reinterpret_cast<const float4*>(
            w1 + (size_t)b * D_DIM * H_DIM);
        const int g     = l & 63;
        const int dbase = (l >> 6) * 64;

        float4 acc = make_float4(0.f, 0.f, 0.f, 0.f);
        #pragma unroll
        for (int i = 0; i < 64; ++i) {
            const int d = dbase + i;
            const float  xv = x_s[d];
            const float4 w  = __ldcs(&w1v[d * (H_DIM / 4) + g]);
            acc.x = fmaf(xv, w.x, acc.x);
            acc.y = fmaf(xv, w.y, acc.y);
            acc.z = fmaf(xv, w.z, acc.z);
            acc.w = fmaf(xv, w.w, acc.w);
        }
        part[l] = acc;
    }
    __syncthreads();

    // reduce 2 partials, add bias, ReLU, write h straight to global
    if (l < 64) {
        float4 s0 = part[l];
        float4 s1 = part[64 + l];
        float4 bb = reinterpret_cast<const float4*>(b1 + (size_t)b * H_DIM)[l];
        float4 h4;
        h4.x = fmaxf(s0.x + s1.x + bb.x, 0.f);
        h4.y = fmaxf(s0.y + s1.y + bb.y, 0.f);
        h4.z = fmaxf(s0.z + s1.z + bb.z, 0.f);
        h4.w = fmaxf(s0.w + s1.w + bb.w, 0.f);
        reinterpret_cast<float4*>(g_h + (size_t)b * H_DIM)[l] = h4;
    }
}

// ==================== Kernel B: sparse predicated GEMV2 ==================
__global__ void __launch_bounds__(128, 8) gemv2_kernel(
    const float* __restrict__ w2,
    const float* __restrict__ b2,
    float* __restrict__ out)
{
    const int l = threadIdx.x;       // 0..127
    const int b = blockIdx.x;

    __shared__ float  h_s[H_DIM];
    __shared__ float4 part[128];

    // stage h[b,:]: 128 threads x float2
    reinterpret_cast<float2*>(h_s)[l] =
        reinterpret_cast<const float2*>(g_h + (size_t)b * H_DIM)[l];
    __syncthreads();

    // out[c] = sum_{j: h[j]>0} h[j] * w2[j, c]
    // w2[b] as float4[256][16]. Thread: (jslot = l>>4 in 0..7, cg = l&15).
    // Row j = jslot + 8*i (affine). h_s[j] uniform across the 16-lane group:
    // predicated-off LDG is free, predicated-on loads batch freely.
    // Own register budget (<=64): R11 showed the sparse loop wants regs.
    {
        const float4* w2v = reinterpret_cast<const float4*>(
            w2 + (size_t)b * H_DIM * C_DIM);
        const int cg    = l & 15;
        const int jslot = l >> 4;

        float4 acc = make_float4(0.f, 0.f, 0.f, 0.f);
        #pragma unroll 16
        for (int i = 0; i < H_DIM / 8; ++i) {
            const int j = jslot + i * 8;
            const float hv = h_s[j];
            if (hv > 0.f) {
                const float4 wv = __ldcs(&w2v[j * (C_DIM / 4) + cg]);
                acc.x = fmaf(hv, wv.x, acc.x);
                acc.y = fmaf(hv, wv.y, acc.y);
                acc.z = fmaf(hv, wv.z, acc.z);
                acc.w = fmaf(hv, wv.w, acc.w);
            }
        }
        part[l] = acc;   // index = jslot*16 + cg
    }
    __syncthreads();

    // reduce 8 jslot-partials per cg, add bias, streaming store
    if (l < 16) {
        float4 acc = part[l];
        #pragma unroll
        for (int k = 1; k < 8; ++k) {
            float4 p = part[k * 16 + l];
            acc.x += p.x; acc.y += p.y; acc.z += p.z; acc.w += p.w;
        }
        float4 bb = reinterpret_cast<const float4*>(b2 + (size_t)b * C_DIM)[l];
        acc.x += bb.x; acc.y += bb.y; acc.z += bb.z; acc.w += bb.w;
        __stcs(reinterpret_cast<float4*>(out + (size_t)b * C_DIM) + l, acc);
    }
}

extern "C" void kernel_launch(void* const* d_in, const int* in_sizes, int n_in,
                              void* d_out, int out_size)
{
    const float* x  = (const float*)d_in[0];
    const float* w1 = (const float*)d_in[1];
    const float* b1 = (const float*)d_in[2];
    const float* w2 = (const float*)d_in[3];
    const float* b2 = (const float*)d_in[4];
    float* out = (float*)d_out;

    gemv1_kernel<<<B_DIM, 128>>>(x, w1, b1);
    gemv2_kernel<<<B_DIM, 128>>>(w2, b2, out);
}

// round 13
// speedup vs baseline: 1.0577x; 1.0577x over previous
#include <cuda_runtime.h>

// Per-sample 2-layer MLP with ReLU-sparsity skipping in layer 2 via
// predicated affine loads, with the predicate DECOUPLED from the load loop.
//   h = relu(x[b,:] @ w1[b,:,:] + b1[b,:])   (D=128 -> H=256)
//   out = h @ w2[b,:,:] + b2[b,:]            (H=256 -> C=64)
// Rows of w2 with h[j]==0 are never loaded (~50% skipped, exact).
// R13 change: each thread pre-builds a 32-bit activity mask (32 pipelined
// independent LDS reads), so the main loop's @P LDGs depend only on register
// bits -> the LDS(29cyc)->FSETP(13cyc)->LDG chain that capped in-flight
// loads in R9/R12 (isolated sparse phase measured 61% DRAM) is gone.
// Everything else is the R9 champion verbatim.

#define B_DIM 4096
#define D_DIM 128
#define H_DIM 256
#define C_DIM 64

__global__ void __launch_bounds__(128, 10) mlp_mask_kernel(
    const float* __restrict__ x,
    const float* __restrict__ w1,
    const float* __restrict__ b1,
    const float* __restrict__ w2,
    const float* __restrict__ b2,
    float* __restrict__ out)
{
    const int l = threadIdx.x;       // 0..127
    const int b = blockIdx.x;

    __shared__ float  x_s[D_DIM];
    __shared__ float  h_s[H_DIM];
    __shared__ float4 part[128];

    // ---- stage x[b,:] ----
    x_s[l] = x[(size_t)b * D_DIM + l];
    __syncthreads();

    // ================= GEMV1: h[j] = sum_d x[d] * w1[d, j] =================
    // w1[b] as float4[128][64]. Thread: (dchunk = l>>6, g = l&63).
    // 64 float4 loads/thread, warp-contiguous 1024B rows. (Proven, unchanged.)
    {
        const float4* w1v = reinterpret_cast<const float4*>(
            w1 + (size_t)b * D_DIM * H_DIM);
        const int g     = l & 63;
        const int dbase = (l >> 6) * 64;

        float4 acc = make_float4(0.f, 0.f, 0.f, 0.f);
        #pragma unroll
        for (int i = 0; i < 64; ++i) {
            const int d = dbase + i;
            const float  xv = x_s[d];
            const float4 w  = __ldcs(&w1v[d * (H_DIM / 4) + g]);
            acc.x = fmaf(xv, w.x, acc.x);
            acc.y = fmaf(xv, w.y, acc.y);
            acc.z = fmaf(xv, w.z, acc.z);
            acc.w = fmaf(xv, w.w, acc.w);
        }
        part[l] = acc;
    }
    __syncthreads();

    // reduce 2 partials, add bias, ReLU -> h_s
    if (l < 64) {
        float4 s0 = part[l];
        float4 s1 = part[64 + l];
        float4 bb = reinterpret_cast<const float4*>(b1 + (size_t)b * H_DIM)[l];
        float4 h4;
        h4.x = fmaxf(s0.x + s1.x + bb.x, 0.f);
        h4.y = fmaxf(s0.y + s1.y + bb.y, 0.f);
        h4.z = fmaxf(s0.z + s1.z + bb.z, 0.f);
        h4.w = fmaxf(s0.w + s1.w + bb.w, 0.f);
        reinterpret_cast<float4*>(h_s)[l] = h4;
    }
    __syncthreads();

    // ========== GEMV2 (sparse, register-mask predication): =================
    // out[c] = sum_{j: h[j]>0} h[j] * w2[j, c]
    // w2[b] as float4[256][16]. Thread: (jslot = l>>4 in 0..7, cg = l&15).
    // Row j = jslot + 8*i (affine).
    {
        const float4* w2v = reinterpret_cast<const float4*>(
            w2 + (size_t)b * H_DIM * C_DIM);
        const int cg    = l & 15;
        const int jslot = l >> 4;

        // Phase 1: build activity mask -- 32 independent pipelined LDS reads.
        unsigned m = 0;
        #pragma unroll
        for (int i = 0; i < 32; ++i)
            m |= (h_s[jslot + i * 8] > 0.f) ? (1u << i) : 0u;

        // Phase 2: load loop. @P from register bits only -> LDGs batch freely.
        float4 acc = make_float4(0.f, 0.f, 0.f, 0.f);
        #pragma unroll
        for (int i = 0; i < 32; ++i) {
            if ((m >> i) & 1u) {
                const int j = jslot + i * 8;
                const float4 wv = __ldcs(&w2v[j * (C_DIM / 4) + cg]);
                const float  hv = h_s[j];
                acc.x = fmaf(hv, wv.x, acc.x);
                acc.y = fmaf(hv, wv.y, acc.y);
                acc.z = fmaf(hv, wv.z, acc.z);
                acc.w = fmaf(hv, wv.w, acc.w);
            }
        }
        part[l] = acc;   // index = jslot*16 + cg
    }
    __syncthreads();

    // reduce 8 jslot-partials per cg, add bias, streaming store
    if (l < 16) {
        float4 acc = part[l];
        #pragma unroll
        for (int k = 1; k < 8; ++k) {
            float4 p = part[k * 16 + l];
            acc.x += p.x; acc.y += p.y; acc.z += p.z; acc.w += p.w;
        }
        float4 bb = reinterpret_cast<const float4*>(b2 + (size_t)b * C_DIM)[l];
        acc.x += bb.x; acc.y += bb.y; acc.z += bb.z; acc.w += bb.w;
        __stcs(reinterpret_cast<float4*>(out + (size_t)b * C_DIM) + l, acc);
    }
}

extern "C" void kernel_launch(void* const* d_in, const int* in_sizes, int n_in,
                              void* d_out, int out_size)
{
    const float* x  = (const float*)d_in[0];
    const float* w1 = (const float*)d_in[1];
    const float* b1 = (const float*)d_in[2];
    const float* w2 = (const float*)d_in[3];
    const float* b2 = (const float*)d_in[4];
    float* out = (float*)d_out;

    mlp_mask_kernel<<<B_DIM, 128>>>(x, w1, b1, w2, b2, out);
}